// round 1
// baseline (speedup 1.0000x reference)
#include <cuda_runtime.h>

#define HD 64
static const int NMAX = 100000;

// Scratch (allocation-free per harness rules)
__device__ int   g_deg[NMAX];
__device__ float g_dinv[NMAX];
__device__ float g_s[NMAX * HD];    // dinv[u] * (in[u] @ W)
__device__ float g_acc[NMAX * HD];  // scatter accumulator
__device__ float g_h[NMAX * HD];    // layer-1 output

__device__ __forceinline__ void red_add_f32x4(float* addr, float4 v) {
    asm volatile("red.global.add.v4.f32 [%0], {%1,%2,%3,%4};"
                 :: "l"(addr), "f"(v.x), "f"(v.y), "f"(v.z), "f"(v.w)
                 : "memory");
}

__global__ void k_init_deg(int n) {
    int i = blockIdx.x * blockDim.x + threadIdx.x;
    if (i < n) g_deg[i] = 1;   // self-loop
}

__global__ void k_count(const int* __restrict__ dst, int e) {
    int i = blockIdx.x * blockDim.x + threadIdx.x;
    if (i < e) atomicAdd(&g_deg[dst[i]], 1);
}

__global__ void k_dinv(int n) {
    int i = blockIdx.x * blockDim.x + threadIdx.x;
    if (i < n) g_dinv[i] = rsqrtf((float)g_deg[i]);
}

__global__ void k_zero_acc(int n) {
    int i = blockIdx.x * blockDim.x + threadIdx.x;
    if (i < n * (HD / 4))
        *reinterpret_cast<float4*>(&g_acc[i * 4]) = make_float4(0.f, 0.f, 0.f, 0.f);
}

// x0 = x @ W_pre + b_pre      x:[n,128]  W:[128,64]  out:[n,64]
__global__ __launch_bounds__(256) void k_gemm_pre(
    const float* __restrict__ x, const float* __restrict__ W,
    const float* __restrict__ b, float* __restrict__ out, int n)
{
    __shared__ float sX[64 * 64];
    __shared__ float sW[64 * 64];
    int row0 = blockIdx.x * 64;
    int t  = threadIdx.x;
    int tx = t & 15, ty = t >> 4;

    float acc[4][4] = {};

    for (int kc = 0; kc < 2; kc++) {
        if (kc) __syncthreads();
        // load X tile [64 rows x 64 k] and W chunk [64 k x 64 cols]
        #pragma unroll
        for (int it = 0; it < 4; it++) {
            int idx = t + it * 256;       // float4 slot
            int r = idx >> 4, c4 = idx & 15;
            float4 v = make_float4(0.f, 0.f, 0.f, 0.f);
            if (row0 + r < n)
                v = *reinterpret_cast<const float4*>(&x[(size_t)(row0 + r) * 128 + kc * 64 + c4 * 4]);
            *reinterpret_cast<float4*>(&sX[r * 64 + c4 * 4]) = v;
            *reinterpret_cast<float4*>(&sW[r * 64 + c4 * 4]) =
                *reinterpret_cast<const float4*>(&W[(size_t)(kc * 64 + r) * 64 + c4 * 4]);
        }
        __syncthreads();
        #pragma unroll 8
        for (int k = 0; k < 64; k++) {
            float4 w = *reinterpret_cast<float4*>(&sW[k * 64 + tx * 4]);
            float a0 = sX[(ty * 4 + 0) * 64 + k];
            float a1 = sX[(ty * 4 + 1) * 64 + k];
            float a2 = sX[(ty * 4 + 2) * 64 + k];
            float a3 = sX[(ty * 4 + 3) * 64 + k];
            acc[0][0] += a0 * w.x; acc[0][1] += a0 * w.y; acc[0][2] += a0 * w.z; acc[0][3] += a0 * w.w;
            acc[1][0] += a1 * w.x; acc[1][1] += a1 * w.y; acc[1][2] += a1 * w.z; acc[1][3] += a1 * w.w;
            acc[2][0] += a2 * w.x; acc[2][1] += a2 * w.y; acc[2][2] += a2 * w.z; acc[2][3] += a2 * w.w;
            acc[3][0] += a3 * w.x; acc[3][1] += a3 * w.y; acc[3][2] += a3 * w.z; acc[3][3] += a3 * w.w;
        }
    }

    float4 bb = *reinterpret_cast<const float4*>(&b[tx * 4]);
    #pragma unroll
    for (int i = 0; i < 4; i++) {
        int r = row0 + ty * 4 + i;
        if (r < n) {
            float4 o = make_float4(acc[i][0] + bb.x, acc[i][1] + bb.y,
                                   acc[i][2] + bb.z, acc[i][3] + bb.w);
            *reinterpret_cast<float4*>(&out[(size_t)r * HD + tx * 4]) = o;
        }
    }
}

// s = dinv[row] * (in @ W)    in:[n,64]  W:[64,64]  -> g_s
__global__ __launch_bounds__(256) void k_gemm64_scale(
    const float* __restrict__ in, const float* __restrict__ W, int n)
{
    __shared__ float sX[64 * 64];
    __shared__ float sW[64 * 64];
    int row0 = blockIdx.x * 64;
    int t  = threadIdx.x;
    int tx = t & 15, ty = t >> 4;

    #pragma unroll
    for (int it = 0; it < 4; it++) {
        int idx = t + it * 256;
        int r = idx >> 4, c4 = idx & 15;
        float4 v = make_float4(0.f, 0.f, 0.f, 0.f);
        if (row0 + r < n)
            v = *reinterpret_cast<const float4*>(&in[(size_t)(row0 + r) * 64 + c4 * 4]);
        *reinterpret_cast<float4*>(&sX[r * 64 + c4 * 4]) = v;
        *reinterpret_cast<float4*>(&sW[r * 64 + c4 * 4]) =
            *reinterpret_cast<const float4*>(&W[(size_t)r * 64 + c4 * 4]);
    }
    __syncthreads();

    float acc[4][4] = {};
    #pragma unroll 8
    for (int k = 0; k < 64; k++) {
        float4 w = *reinterpret_cast<float4*>(&sW[k * 64 + tx * 4]);
        float a0 = sX[(ty * 4 + 0) * 64 + k];
        float a1 = sX[(ty * 4 + 1) * 64 + k];
        float a2 = sX[(ty * 4 + 2) * 64 + k];
        float a3 = sX[(ty * 4 + 3) * 64 + k];
        acc[0][0] += a0 * w.x; acc[0][1] += a0 * w.y; acc[0][2] += a0 * w.z; acc[0][3] += a0 * w.w;
        acc[1][0] += a1 * w.x; acc[1][1] += a1 * w.y; acc[1][2] += a1 * w.z; acc[1][3] += a1 * w.w;
        acc[2][0] += a2 * w.x; acc[2][1] += a2 * w.y; acc[2][2] += a2 * w.z; acc[2][3] += a2 * w.w;
        acc[3][0] += a3 * w.x; acc[3][1] += a3 * w.y; acc[3][2] += a3 * w.z; acc[3][3] += a3 * w.w;
    }

    #pragma unroll
    for (int i = 0; i < 4; i++) {
        int r = row0 + ty * 4 + i;
        if (r < n) {
            float d = g_dinv[r];
            float4 o = make_float4(acc[i][0] * d, acc[i][1] * d,
                                   acc[i][2] * d, acc[i][3] * d);
            *reinterpret_cast<float4*>(&g_s[(size_t)r * HD + tx * 4]) = o;
        }
    }
}

// acc[dst] += s[src], 16 threads (float4 each) per edge
__global__ void k_scatter(const int* __restrict__ src, const int* __restrict__ dst, int e) {
    int i = blockIdx.x * blockDim.x + threadIdx.x;
    int ei = i >> 4;
    if (ei >= e) return;
    int c = (i & 15) << 2;
    int u = __ldg(&src[ei]);
    int v = __ldg(&dst[ei]);
    float4 val = *reinterpret_cast<const float4*>(&g_s[(size_t)u * HD + c]);
    red_add_f32x4(&g_acc[(size_t)v * HD + c], val);
}

// out = relu(dinv[v]*(acc[v] + s[v]) + b)  ; s[v] term = self loop
__global__ void k_final(const float* __restrict__ b, float* __restrict__ out, int n) {
    int i = blockIdx.x * blockDim.x + threadIdx.x;
    if (i >= n * (HD / 4)) return;
    int v = i >> 4, c = (i & 15) << 2;
    float d = g_dinv[v];
    float4 a  = *reinterpret_cast<float4*>(&g_acc[(size_t)v * HD + c]);
    float4 s  = *reinterpret_cast<float4*>(&g_s[(size_t)v * HD + c]);
    float4 bb = *reinterpret_cast<const float4*>(&b[c]);
    float4 o;
    o.x = fmaxf(fmaf(d, a.x + s.x, bb.x), 0.f);
    o.y = fmaxf(fmaf(d, a.y + s.y, bb.y), 0.f);
    o.z = fmaxf(fmaf(d, a.z + s.z, bb.z), 0.f);
    o.w = fmaxf(fmaf(d, a.w + s.w, bb.w), 0.f);
    *reinterpret_cast<float4*>(&out[(size_t)v * HD + c]) = o;
}

extern "C" void kernel_launch(void* const* d_in, const int* in_sizes, int n_in,
                              void* d_out, int out_size) {
    const float* x     = (const float*)d_in[0];
    const int*   eidx  = (const int*)  d_in[1];
    const float* W_pre = (const float*)d_in[2];
    const float* b_pre = (const float*)d_in[3];
    const float* W1    = (const float*)d_in[4];
    const float* b1    = (const float*)d_in[5];
    const float* W2    = (const float*)d_in[6];
    const float* b2    = (const float*)d_in[7];
    float* out = (float*)d_out;

    int n = in_sizes[0] / 128;
    int e = in_sizes[1] / 2;
    const int* src = eidx;
    const int* dst = eidx + e;

    float* x_out  = out;                    // final layer-2 output
    float* ori_x  = out + (size_t)n * HD;   // pre-linear output

    float* h_buf = nullptr;
    cudaGetSymbolAddress((void**)&h_buf, g_h);

    const int T = 256;
    int gb_n   = (n + T - 1) / T;
    int gb_e   = (e + T - 1) / T;
    int gb_n16 = (n * (HD / 4) + T - 1) / T;
    int gb_e16 = (e * (HD / 4) + T - 1) / T;
    int gb_g   = (n + 63) / 64;

    // degrees (with self-loop) and D^{-1/2}
    k_init_deg<<<gb_n, T>>>(n);
    k_count<<<gb_e, T>>>(dst, e);
    k_dinv<<<gb_n, T>>>(n);

    // pre-linear: ori_x = x @ W_pre + b_pre
    k_gemm_pre<<<gb_g, T>>>(x, W_pre, b_pre, ori_x, n);

    // layer 1: h = relu(GCNConv(ori_x, W1, b1))
    k_zero_acc<<<gb_n16, T>>>(n);
    k_gemm64_scale<<<gb_g, T>>>(ori_x, W1, n);
    k_scatter<<<gb_e16, T>>>(src, dst, e);
    k_final<<<gb_n16, T>>>(b1, h_buf, n);

    // layer 2: x_out = relu(GCNConv(h, W2, b2))
    k_zero_acc<<<gb_n16, T>>>(n);
    k_gemm64_scale<<<gb_g, T>>>(h_buf, W2, n);
    k_scatter<<<gb_e16, T>>>(src, dst, e);
    k_final<<<gb_n16, T>>>(b2, x_out, n);
}

// round 6
// speedup vs baseline: 1.4596x; 1.4596x over previous
#include <cuda_runtime.h>

#define HD 64
static const int NMAX = 100000;
static const int EMAX = 1200000;

// Scratch (allocation-free per harness rules)
__device__ int   g_deg[NMAX];
__device__ int   g_off[NMAX + 1];
__device__ int   g_cur[NMAX];
__device__ int   g_part[1024];
__device__ int   g_csr[EMAX];
__device__ float g_dinv[NMAX];
__device__ float g_s[NMAX * HD];    // dinv[u] * (in[u] @ W)
__device__ float g_h[NMAX * HD];    // layer-1 output

// ---------- packed f32x2 helpers ----------
__device__ __forceinline__ unsigned long long pack2(float a) {
    unsigned long long r;
    asm("mov.b64 %0, {%1, %1};" : "=l"(r) : "f"(a));
    return r;
}
__device__ __forceinline__ void fma2(unsigned long long& d,
                                     unsigned long long a,
                                     unsigned long long b) {
    asm("fma.rn.f32x2 %0, %1, %2, %0;" : "+l"(d) : "l"(a), "l"(b));
}
__device__ __forceinline__ float2 unpack2(unsigned long long v) {
    float2 u;
    asm("mov.b64 {%0, %1}, %2;" : "=f"(u.x), "=f"(u.y) : "l"(v));
    return u;
}

// ---------- graph preprocessing ----------
__global__ void k_zero_deg(int n) {
    int i = blockIdx.x * blockDim.x + threadIdx.x;
    if (i < n) g_deg[i] = 0;
}

__global__ void k_count(const int* __restrict__ dst, int e) {
    int i = blockIdx.x * blockDim.x + threadIdx.x;
    if (i < e) {
        int d = dst[i];
        if (d >= 0 && d < NMAX) atomicAdd(&g_deg[d], 1);
    }
}

#define SCAN_B 512
// pass 1: per-block exclusive scan of degrees into g_off, block totals into g_part
__global__ __launch_bounds__(SCAN_B) void k_scan1(int n) {
    __shared__ int sh[SCAN_B];
    int i = blockIdx.x * SCAN_B + threadIdx.x;
    int v = (i < n) ? g_deg[i] : 0;
    sh[threadIdx.x] = v;
    __syncthreads();
    #pragma unroll
    for (int d = 1; d < SCAN_B; d <<= 1) {
        int x = (threadIdx.x >= d) ? sh[threadIdx.x - d] : 0;
        __syncthreads();
        sh[threadIdx.x] += x;
        __syncthreads();
    }
    if (i < n) g_off[i] = sh[threadIdx.x] - v;   // exclusive within block
    if (threadIdx.x == SCAN_B - 1) g_part[blockIdx.x] = sh[SCAN_B - 1];
}

// pass 2: exclusive scan of the (<=1024) block totals
__global__ __launch_bounds__(1024) void k_scan2(int nb) {
    __shared__ int sh[1024];
    int v = (threadIdx.x < nb) ? g_part[threadIdx.x] : 0;
    sh[threadIdx.x] = v;
    __syncthreads();
    #pragma unroll
    for (int d = 1; d < 1024; d <<= 1) {
        int x = (threadIdx.x >= d) ? sh[threadIdx.x - d] : 0;
        __syncthreads();
        sh[threadIdx.x] += x;
        __syncthreads();
    }
    if (threadIdx.x < nb) g_part[threadIdx.x] = sh[threadIdx.x] - v;
}

// pass 3: add block prefix; init cursors; dinv = rsqrt(deg + 1 self-loop)
__global__ __launch_bounds__(SCAN_B) void k_scan3(int n, int e) {
    int i = blockIdx.x * SCAN_B + threadIdx.x;
    if (i < n) {
        int o = g_off[i] + g_part[blockIdx.x];
        g_off[i] = o;
        g_cur[i] = o;
        g_dinv[i] = rsqrtf((float)(g_deg[i] + 1));
    }
    if (i == 0) g_off[n] = e;
}

__global__ void k_fill(const int* __restrict__ src, const int* __restrict__ dst, int e) {
    int i = blockIdx.x * blockDim.x + threadIdx.x;
    if (i < e) {
        int d = dst[i];
        if (d >= 0 && d < NMAX) {
            int pos = atomicAdd(&g_cur[d], 1);
            if (pos >= 0 && pos < EMAX) g_csr[pos] = src[i];
        }
    }
}

// ---------- GEMMs (packed f32x2 FMA) ----------
#define SXS 68   // padded row stride for sX (kills 2-way bank conflict)

// out = x @ W_pre + b      x:[n,128]  W:[128,64]
__global__ __launch_bounds__(256) void k_gemm_pre(
    const float* __restrict__ x, const float* __restrict__ W,
    const float* __restrict__ b, float* __restrict__ out, int n)
{
    __shared__ float sX[64 * SXS];
    __shared__ float sW[64 * 64];
    int row0 = blockIdx.x * 64;
    int t = threadIdx.x;
    int tx = t & 15, ty = t >> 4;

    unsigned long long acc[4][2] = {};   // 4 rows x (2 cols packed) x2

    for (int kc = 0; kc < 2; kc++) {
        if (kc) __syncthreads();
        #pragma unroll
        for (int it = 0; it < 4; it++) {
            int idx = t + it * 256;
            int r = idx >> 4, c4 = idx & 15;
            float4 v = make_float4(0.f, 0.f, 0.f, 0.f);
            if (row0 + r < n)
                v = *reinterpret_cast<const float4*>(&x[(size_t)(row0 + r) * 128 + kc * 64 + c4 * 4]);
            *reinterpret_cast<float4*>(&sX[r * SXS + c4 * 4]) = v;
            *reinterpret_cast<float4*>(&sW[r * 64 + c4 * 4]) =
                *reinterpret_cast<const float4*>(&W[(size_t)(kc * 64 + r) * 64 + c4 * 4]);
        }
        __syncthreads();
        #pragma unroll 8
        for (int k = 0; k < 64; k++) {
            ulonglong2 w = *reinterpret_cast<ulonglong2*>(&sW[k * 64 + tx * 4]);
            #pragma unroll
            for (int i = 0; i < 4; i++) {
                unsigned long long ap = pack2(sX[(ty * 4 + i) * SXS + k]);
                fma2(acc[i][0], ap, w.x);
                fma2(acc[i][1], ap, w.y);
            }
        }
    }

    float4 bb = *reinterpret_cast<const float4*>(&b[tx * 4]);
    #pragma unroll
    for (int i = 0; i < 4; i++) {
        int r = row0 + ty * 4 + i;
        if (r < n) {
            float2 lo = unpack2(acc[i][0]);
            float2 hi = unpack2(acc[i][1]);
            float4 o = make_float4(lo.x + bb.x, lo.y + bb.y, hi.x + bb.z, hi.y + bb.w);
            *reinterpret_cast<float4*>(&out[(size_t)r * HD + tx * 4]) = o;
        }
    }
}

// g_s = dinv[row] * (in @ W)    in:[n,64]  W:[64,64]
__global__ __launch_bounds__(256) void k_gemm64_scale(
    const float* __restrict__ in, const float* __restrict__ W, int n)
{
    __shared__ float sX[64 * SXS];
    __shared__ float sW[64 * 64];
    int row0 = blockIdx.x * 64;
    int t = threadIdx.x;
    int tx = t & 15, ty = t >> 4;

    #pragma unroll
    for (int it = 0; it < 4; it++) {
        int idx = t + it * 256;
        int r = idx >> 4, c4 = idx & 15;
        float4 v = make_float4(0.f, 0.f, 0.f, 0.f);
        if (row0 + r < n)
            v = *reinterpret_cast<const float4*>(&in[(size_t)(row0 + r) * 64 + c4 * 4]);
        *reinterpret_cast<float4*>(&sX[r * SXS + c4 * 4]) = v;
        *reinterpret_cast<float4*>(&sW[r * 64 + c4 * 4]) =
            *reinterpret_cast<const float4*>(&W[(size_t)r * 64 + c4 * 4]);
    }
    __syncthreads();

    unsigned long long acc[4][2] = {};
    #pragma unroll 8
    for (int k = 0; k < 64; k++) {
        ulonglong2 w = *reinterpret_cast<ulonglong2*>(&sW[k * 64 + tx * 4]);
        #pragma unroll
        for (int i = 0; i < 4; i++) {
            unsigned long long ap = pack2(sX[(ty * 4 + i) * SXS + k]);
            fma2(acc[i][0], ap, w.x);
            fma2(acc[i][1], ap, w.y);
        }
    }

    #pragma unroll
    for (int i = 0; i < 4; i++) {
        int r = row0 + ty * 4 + i;
        if (r < n) {
            float d = g_dinv[r];
            float2 lo = unpack2(acc[i][0]);
            float2 hi = unpack2(acc[i][1]);
            float4 o = make_float4(lo.x * d, lo.y * d, hi.x * d, hi.y * d);
            *reinterpret_cast<float4*>(&g_s[(size_t)r * HD + tx * 4]) = o;
        }
    }
}

// ---------- fused pull-gather + norm + bias + relu ----------
// out[v] = relu(dinv[v] * (sum_{u in N(v)} s[u] + s[v]) + b)
__global__ __launch_bounds__(256) void k_gather(
    const float* __restrict__ b, float* __restrict__ out, int n)
{
    int v = blockIdx.x * 16 + (threadIdx.x >> 4);
    if (v >= n) return;
    int c = (threadIdx.x & 15) * 4;

    int beg = g_off[v];
    int end = g_off[v + 1];

    float4 acc = *reinterpret_cast<const float4*>(&g_s[(size_t)v * HD + c]);  // self-loop

    int j = beg;
    for (; j + 4 <= end; j += 4) {
        int u0 = __ldg(&g_csr[j]);
        int u1 = __ldg(&g_csr[j + 1]);
        int u2 = __ldg(&g_csr[j + 2]);
        int u3 = __ldg(&g_csr[j + 3]);
        float4 a0 = *reinterpret_cast<const float4*>(&g_s[(size_t)u0 * HD + c]);
        float4 a1 = *reinterpret_cast<const float4*>(&g_s[(size_t)u1 * HD + c]);
        float4 a2 = *reinterpret_cast<const float4*>(&g_s[(size_t)u2 * HD + c]);
        float4 a3 = *reinterpret_cast<const float4*>(&g_s[(size_t)u3 * HD + c]);
        acc.x += (a0.x + a1.x) + (a2.x + a3.x);
        acc.y += (a0.y + a1.y) + (a2.y + a3.y);
        acc.z += (a0.z + a1.z) + (a2.z + a3.z);
        acc.w += (a0.w + a1.w) + (a2.w + a3.w);
    }
    for (; j < end; j++) {
        int u = __ldg(&g_csr[j]);
        float4 a = *reinterpret_cast<const float4*>(&g_s[(size_t)u * HD + c]);
        acc.x += a.x; acc.y += a.y; acc.z += a.z; acc.w += a.w;
    }

    float d = g_dinv[v];
    float4 bb = *reinterpret_cast<const float4*>(&b[c]);
    float4 o;
    o.x = fmaxf(fmaf(d, acc.x, bb.x), 0.f);
    o.y = fmaxf(fmaf(d, acc.y, bb.y), 0.f);
    o.z = fmaxf(fmaf(d, acc.z, bb.z), 0.f);
    o.w = fmaxf(fmaf(d, acc.w, bb.w), 0.f);
    *reinterpret_cast<float4*>(&out[(size_t)v * HD + c]) = o;
}

extern "C" void kernel_launch(void* const* d_in, const int* in_sizes, int n_in,
                              void* d_out, int out_size) {
    const float* x     = (const float*)d_in[0];
    const int*   eidx  = (const int*)  d_in[1];
    const float* W_pre = (const float*)d_in[2];
    const float* b_pre = (const float*)d_in[3];
    const float* W1    = (const float*)d_in[4];
    const float* b1    = (const float*)d_in[5];
    const float* W2    = (const float*)d_in[6];
    const float* b2    = (const float*)d_in[7];
    float* out = (float*)d_out;

    int n = in_sizes[0] / 128;
    int e = in_sizes[1] / 2;
    const int* src = eidx;
    const int* dst = eidx + e;

    float* x_out = out;                    // layer-2 output
    float* ori_x = out + (size_t)n * HD;   // pre-linear output

    float* h_buf = nullptr;
    cudaGetSymbolAddress((void**)&h_buf, g_h);

    const int T = 256;
    int gb_n = (n + T - 1) / T;
    int gb_e = (e + T - 1) / T;
    int gb_g = (n + 63) / 64;
    int nb   = (n + SCAN_B - 1) / SCAN_B;
    int gb_a = (n + 15) / 16;

    // CSR build (degree -> offsets -> fill) + dinv
    k_zero_deg<<<gb_n, T>>>(n);
    k_count<<<gb_e, T>>>(dst, e);
    k_scan1<<<nb, SCAN_B>>>(n);
    k_scan2<<<1, 1024>>>(nb);
    k_scan3<<<nb, SCAN_B>>>(n, e);
    k_fill<<<gb_e, T>>>(src, dst, e);

    // pre-linear: ori_x = x @ W_pre + b_pre
    k_gemm_pre<<<gb_g, T>>>(x, W_pre, b_pre, ori_x, n);

    // layer 1
    k_gemm64_scale<<<gb_g, T>>>(ori_x, W1, n);
    k_gather<<<gb_a, T>>>(b1, h_buf, n);

    // layer 2
    k_gemm64_scale<<<gb_g, T>>>(h_buf, W2, n);
    k_gather<<<gb_a, T>>>(b2, x_out, n);
}

// round 9
// speedup vs baseline: 1.5057x; 1.0316x over previous
#include <cuda_runtime.h>
#include <cuda_fp16.h>

#define HD 64
static const int NMAX = 100000;
static const int EMAX = 1200000;

// Scratch (allocation-free per harness rules)
__device__ int    g_deg[NMAX];
__device__ int    g_off[NMAX + 1];
__device__ int    g_cur[NMAX];
__device__ int    g_part[1024];
__device__ int    g_csr[EMAX];
__device__ float  g_dinv[NMAX];
__device__ __half g_sh[NMAX * HD];   // fp16: dinv[u] * (in[u] @ W)
__device__ float  g_h[NMAX * HD];    // layer-1 output (fp32)

// ---------- packed f32x2 helpers ----------
__device__ __forceinline__ unsigned long long pack2(float a) {
    unsigned long long r;
    asm("mov.b64 %0, {%1, %1};" : "=l"(r) : "f"(a));
    return r;
}
__device__ __forceinline__ void fma2(unsigned long long& d,
                                     unsigned long long a,
                                     unsigned long long b) {
    asm("fma.rn.f32x2 %0, %1, %2, %0;" : "+l"(d) : "l"(a), "l"(b));
}
__device__ __forceinline__ float2 unpack2(unsigned long long v) {
    float2 u;
    asm("mov.b64 {%0, %1}, %2;" : "=f"(u.x), "=f"(u.y) : "l"(v));
    return u;
}

// ---------- graph preprocessing ----------
__global__ void k_zero_deg(int n) {
    int i = blockIdx.x * blockDim.x + threadIdx.x;
    if (i < n) g_deg[i] = 0;
}

__global__ void k_count(const int* __restrict__ dst, int e) {
    int i = blockIdx.x * blockDim.x + threadIdx.x;
    if (i < e) {
        int d = dst[i];
        if (d >= 0 && d < NMAX) atomicAdd(&g_deg[d], 1);
    }
}

#define SCAN_B 512
// pass 1: per-block exclusive scan (warp shuffle) -> g_off, totals -> g_part
__global__ __launch_bounds__(SCAN_B) void k_scan1(int n) {
    __shared__ int warp_sums[SCAN_B / 32];
    int i = blockIdx.x * SCAN_B + threadIdx.x;
    int v = (i < n) ? g_deg[i] : 0;
    int lane = threadIdx.x & 31, wid = threadIdx.x >> 5;

    int s = v;
    #pragma unroll
    for (int d = 1; d < 32; d <<= 1) {
        int t = __shfl_up_sync(0xffffffffu, s, d);
        if (lane >= d) s += t;
    }
    if (lane == 31) warp_sums[wid] = s;
    __syncthreads();
    if (wid == 0) {
        int ws = (lane < SCAN_B / 32) ? warp_sums[lane] : 0;
        #pragma unroll
        for (int d = 1; d < SCAN_B / 32; d <<= 1) {
            int t = __shfl_up_sync(0xffffffffu, ws, d);
            if (lane >= d) ws += t;
        }
        if (lane < SCAN_B / 32) warp_sums[lane] = ws;
    }
    __syncthreads();
    int base = (wid > 0) ? warp_sums[wid - 1] : 0;
    int incl = base + s;
    if (i < n) g_off[i] = incl - v;            // exclusive within block
    if (threadIdx.x == SCAN_B - 1) g_part[blockIdx.x] = incl;
}

// pass 2: exclusive scan of the (<=1024) block totals, warp shuffle
__global__ __launch_bounds__(1024) void k_scan2(int nb) {
    __shared__ int warp_sums[32];
    int v = (threadIdx.x < nb) ? g_part[threadIdx.x] : 0;
    int lane = threadIdx.x & 31, wid = threadIdx.x >> 5;

    int s = v;
    #pragma unroll
    for (int d = 1; d < 32; d <<= 1) {
        int t = __shfl_up_sync(0xffffffffu, s, d);
        if (lane >= d) s += t;
    }
    if (lane == 31) warp_sums[wid] = s;
    __syncthreads();
    if (wid == 0) {
        int ws = warp_sums[lane];
        #pragma unroll
        for (int d = 1; d < 32; d <<= 1) {
            int t = __shfl_up_sync(0xffffffffu, ws, d);
            if (lane >= d) ws += t;
        }
        warp_sums[lane] = ws;
    }
    __syncthreads();
    int base = (wid > 0) ? warp_sums[wid - 1] : 0;
    if (threadIdx.x < nb) g_part[threadIdx.x] = base + s - v;
}

// pass 3: add block prefix; init cursors; dinv = rsqrt(deg + 1 self-loop)
__global__ __launch_bounds__(SCAN_B) void k_scan3(int n, int e) {
    int i = blockIdx.x * SCAN_B + threadIdx.x;
    if (i < n) {
        int o = g_off[i] + g_part[blockIdx.x];
        g_off[i] = o;
        g_cur[i] = o;
        g_dinv[i] = rsqrtf((float)(g_deg[i] + 1));
    }
    if (i == 0) g_off[n] = e;
}

__global__ void k_fill(const int* __restrict__ src, const int* __restrict__ dst, int e) {
    int i = blockIdx.x * blockDim.x + threadIdx.x;
    if (i < e) {
        int d = dst[i];
        if (d >= 0 && d < NMAX) {
            int pos = atomicAdd(&g_cur[d], 1);
            if (pos >= 0 && pos < EMAX) g_csr[pos] = src[i];
        }
    }
}

// ---------- GEMMs (packed f32x2 FMA) ----------
#define SXS 68   // padded row stride for sX (kills 2-way bank conflict)

// out = x @ W_pre + b      x:[n,128]  W:[128,64]  (fp32 out = ori_x)
__global__ __launch_bounds__(256) void k_gemm_pre(
    const float* __restrict__ x, const float* __restrict__ W,
    const float* __restrict__ b, float* __restrict__ out, int n)
{
    __shared__ float sX[64 * SXS];
    __shared__ float sW[64 * 64];
    int row0 = blockIdx.x * 64;
    int t = threadIdx.x;
    int tx = t & 15, ty = t >> 4;

    unsigned long long acc[4][2] = {};

    for (int kc = 0; kc < 2; kc++) {
        if (kc) __syncthreads();
        #pragma unroll
        for (int it = 0; it < 4; it++) {
            int idx = t + it * 256;
            int r = idx >> 4, c4 = idx & 15;
            float4 v = make_float4(0.f, 0.f, 0.f, 0.f);
            if (row0 + r < n)
                v = *reinterpret_cast<const float4*>(&x[(size_t)(row0 + r) * 128 + kc * 64 + c4 * 4]);
            *reinterpret_cast<float4*>(&sX[r * SXS + c4 * 4]) = v;
            *reinterpret_cast<float4*>(&sW[r * 64 + c4 * 4]) =
                *reinterpret_cast<const float4*>(&W[(size_t)(kc * 64 + r) * 64 + c4 * 4]);
        }
        __syncthreads();
        #pragma unroll 8
        for (int k = 0; k < 64; k++) {
            ulonglong2 w = *reinterpret_cast<ulonglong2*>(&sW[k * 64 + tx * 4]);
            #pragma unroll
            for (int i = 0; i < 4; i++) {
                unsigned long long ap = pack2(sX[(ty * 4 + i) * SXS + k]);
                fma2(acc[i][0], ap, w.x);
                fma2(acc[i][1], ap, w.y);
            }
        }
    }

    float4 bb = *reinterpret_cast<const float4*>(&b[tx * 4]);
    #pragma unroll
    for (int i = 0; i < 4; i++) {
        int r = row0 + ty * 4 + i;
        if (r < n) {
            float2 lo = unpack2(acc[i][0]);
            float2 hi = unpack2(acc[i][1]);
            float4 o = make_float4(lo.x + bb.x, lo.y + bb.y, hi.x + bb.z, hi.y + bb.w);
            *reinterpret_cast<float4*>(&out[(size_t)r * HD + tx * 4]) = o;
        }
    }
}

// g_sh = fp16( dinv[row] * (in @ W) )    in:[n,64] fp32  W:[64,64]
__global__ __launch_bounds__(256) void k_gemm64_scale(
    const float* __restrict__ in, const float* __restrict__ W, int n)
{
    __shared__ float sX[64 * SXS];
    __shared__ float sW[64 * 64];
    int row0 = blockIdx.x * 64;
    int t = threadIdx.x;
    int tx = t & 15, ty = t >> 4;

    #pragma unroll
    for (int it = 0; it < 4; it++) {
        int idx = t + it * 256;
        int r = idx >> 4, c4 = idx & 15;
        float4 v = make_float4(0.f, 0.f, 0.f, 0.f);
        if (row0 + r < n)
            v = *reinterpret_cast<const float4*>(&in[(size_t)(row0 + r) * 64 + c4 * 4]);
        *reinterpret_cast<float4*>(&sX[r * SXS + c4 * 4]) = v;
        *reinterpret_cast<float4*>(&sW[r * 64 + c4 * 4]) =
            *reinterpret_cast<const float4*>(&W[(size_t)r * 64 + c4 * 4]);
    }
    __syncthreads();

    unsigned long long acc[4][2] = {};
    #pragma unroll 8
    for (int k = 0; k < 64; k++) {
        ulonglong2 w = *reinterpret_cast<ulonglong2*>(&sW[k * 64 + tx * 4]);
        #pragma unroll
        for (int i = 0; i < 4; i++) {
            unsigned long long ap = pack2(sX[(ty * 4 + i) * SXS + k]);
            fma2(acc[i][0], ap, w.x);
            fma2(acc[i][1], ap, w.y);
        }
    }

    #pragma unroll
    for (int i = 0; i < 4; i++) {
        int r = row0 + ty * 4 + i;
        if (r < n) {
            float d = g_dinv[r];
            float2 lo = unpack2(acc[i][0]);
            float2 hi = unpack2(acc[i][1]);
            __half2 h0 = __floats2half2_rn(lo.x * d, lo.y * d);
            __half2 h1 = __floats2half2_rn(hi.x * d, hi.y * d);
            uint2 o;
            o.x = *reinterpret_cast<unsigned int*>(&h0);
            o.y = *reinterpret_cast<unsigned int*>(&h1);
            *reinterpret_cast<uint2*>(&g_sh[(size_t)r * HD + tx * 4]) = o;
        }
    }
}

// load 4 halfs of s[u] at column c, as float4
__device__ __forceinline__ float4 ld_s4(int u, int c) {
    uint2 p = *reinterpret_cast<const uint2*>(&g_sh[(size_t)u * HD + c]);
    __half2 a = *reinterpret_cast<__half2*>(&p.x);
    __half2 b = *reinterpret_cast<__half2*>(&p.y);
    float2 fa = __half22float2(a), fb = __half22float2(b);
    return make_float4(fa.x, fa.y, fb.x, fb.y);
}

// ---------- fused pull-gather + norm + bias + relu ----------
// out[v] = relu(dinv[v] * (sum_{u in N(v)} s[u] + s[v]) + b)
__global__ __launch_bounds__(256) void k_gather(
    const float* __restrict__ b, float* __restrict__ out, int n)
{
    int v = blockIdx.x * 16 + (threadIdx.x >> 4);
    if (v >= n) return;
    int c = (threadIdx.x & 15) * 4;

    int beg = g_off[v];
    int end = g_off[v + 1];

    float4 acc = ld_s4(v, c);    // self-loop

    int j = beg;
    for (; j + 4 <= end; j += 4) {
        int u0 = __ldg(&g_csr[j]);
        int u1 = __ldg(&g_csr[j + 1]);
        int u2 = __ldg(&g_csr[j + 2]);
        int u3 = __ldg(&g_csr[j + 3]);
        float4 a0 = ld_s4(u0, c);
        float4 a1 = ld_s4(u1, c);
        float4 a2 = ld_s4(u2, c);
        float4 a3 = ld_s4(u3, c);
        acc.x += (a0.x + a1.x) + (a2.x + a3.x);
        acc.y += (a0.y + a1.y) + (a2.y + a3.y);
        acc.z += (a0.z + a1.z) + (a2.z + a3.z);
        acc.w += (a0.w + a1.w) + (a2.w + a3.w);
    }
    for (; j < end; j++) {
        int u = __ldg(&g_csr[j]);
        float4 a = ld_s4(u, c);
        acc.x += a.x; acc.y += a.y; acc.z += a.z; acc.w += a.w;
    }

    float d = g_dinv[v];
    float4 bb = *reinterpret_cast<const float4*>(&b[c]);
    float4 o;
    o.x = fmaxf(fmaf(d, acc.x, bb.x), 0.f);
    o.y = fmaxf(fmaf(d, acc.y, bb.y), 0.f);
    o.z = fmaxf(fmaf(d, acc.z, bb.z), 0.f);
    o.w = fmaxf(fmaf(d, acc.w, bb.w), 0.f);
    *reinterpret_cast<float4*>(&out[(size_t)v * HD + c]) = o;
}

extern "C" void kernel_launch(void* const* d_in, const int* in_sizes, int n_in,
                              void* d_out, int out_size) {
    const float* x     = (const float*)d_in[0];
    const int*   eidx  = (const int*)  d_in[1];
    const float* W_pre = (const float*)d_in[2];
    const float* b_pre = (const float*)d_in[3];
    const float* W1    = (const float*)d_in[4];
    const float* b1    = (const float*)d_in[5];
    const float* W2    = (const float*)d_in[6];
    const float* b2    = (const float*)d_in[7];
    float* out = (float*)d_out;

    int n = in_sizes[0] / 128;
    int e = in_sizes[1] / 2;
    const int* src = eidx;
    const int* dst = eidx + e;

    float* x_out = out;                    // layer-2 output
    float* ori_x = out + (size_t)n * HD;   // pre-linear output

    float* h_buf = nullptr;
    cudaGetSymbolAddress((void**)&h_buf, g_h);

    const int T = 256;
    int gb_n = (n + T - 1) / T;
    int gb_e = (e + T - 1) / T;
    int gb_g = (n + 63) / 64;
    int nb   = (n + SCAN_B - 1) / SCAN_B;
    int gb_a = (n + 15) / 16;

    // CSR build (degree -> offsets -> fill) + dinv
    k_zero_deg<<<gb_n, T>>>(n);
    k_count<<<gb_e, T>>>(dst, e);
    k_scan1<<<nb, SCAN_B>>>(n);
    k_scan2<<<1, 1024>>>(nb);
    k_scan3<<<nb, SCAN_B>>>(n, e);
    k_fill<<<gb_e, T>>>(src, dst, e);

    // pre-linear: ori_x = x @ W_pre + b_pre
    k_gemm_pre<<<gb_g, T>>>(x, W_pre, b_pre, ori_x, n);

    // layer 1
    k_gemm64_scale<<<gb_g, T>>>(ori_x, W1, n);
    k_gather<<<gb_a, T>>>(b1, h_buf, n);

    // layer 2
    k_gemm64_scale<<<gb_g, T>>>(h_buf, W2, n);
    k_gather<<<gb_a, T>>>(b2, x_out, n);
}

// round 10
// speedup vs baseline: 1.6112x; 1.0700x over previous
#include <cuda_runtime.h>
#include <cuda_fp16.h>

#define HD 64
static const int NMAX = 100000;
static const int EMAX = 1200000;

// Scratch (allocation-free per harness rules)
__device__ int    g_deg[NMAX];
__device__ int    g_off[NMAX + 1];
__device__ int    g_cur[NMAX];
__device__ int    g_part[1024];
__device__ int    g_csr[EMAX];
__device__ float  g_dinv[NMAX];
__device__ __half g_sh[NMAX * HD];   // fp16: (in[u] @ W), dinv NOT folded
__device__ float  g_h[NMAX * HD];    // layer-1 output (fp32)

// ---------- packed f32x2 helpers ----------
__device__ __forceinline__ unsigned long long pack2(float a) {
    unsigned long long r;
    asm("mov.b64 %0, {%1, %1};" : "=l"(r) : "f"(a));
    return r;
}
__device__ __forceinline__ void fma2(unsigned long long& d,
                                     unsigned long long a,
                                     unsigned long long b) {
    asm("fma.rn.f32x2 %0, %1, %2, %0;" : "+l"(d) : "l"(a), "l"(b));
}
__device__ __forceinline__ float2 unpack2(unsigned long long v) {
    float2 u;
    asm("mov.b64 {%0, %1}, %2;" : "=f"(u.x), "=f"(u.y) : "l"(v));
    return u;
}

// ---------- graph preprocessing (branch A) ----------
__global__ void k_zero_deg(int n) {
    int i = blockIdx.x * blockDim.x + threadIdx.x;
    if (i < n) g_deg[i] = 0;
}

__global__ void k_count(const int* __restrict__ dst, int e) {
    int i = blockIdx.x * blockDim.x + threadIdx.x;
    if (i < e) {
        int d = dst[i];
        if (d >= 0 && d < NMAX) atomicAdd(&g_deg[d], 1);
    }
}

#define SCAN_B 512
// pass 1: per-block exclusive scan (warp shuffle) -> g_off, inclusive totals -> g_part
__global__ __launch_bounds__(SCAN_B) void k_scan1(int n) {
    __shared__ int warp_sums[SCAN_B / 32];
    int i = blockIdx.x * SCAN_B + threadIdx.x;
    int v = (i < n) ? g_deg[i] : 0;
    int lane = threadIdx.x & 31, wid = threadIdx.x >> 5;

    int s = v;
    #pragma unroll
    for (int d = 1; d < 32; d <<= 1) {
        int t = __shfl_up_sync(0xffffffffu, s, d);
        if (lane >= d) s += t;
    }
    if (lane == 31) warp_sums[wid] = s;
    __syncthreads();
    if (wid == 0) {
        int ws = (lane < SCAN_B / 32) ? warp_sums[lane] : 0;
        #pragma unroll
        for (int d = 1; d < SCAN_B / 32; d <<= 1) {
            int t = __shfl_up_sync(0xffffffffu, ws, d);
            if (lane >= d) ws += t;
        }
        if (lane < SCAN_B / 32) warp_sums[lane] = ws;
    }
    __syncthreads();
    int base = (wid > 0) ? warp_sums[wid - 1] : 0;
    int incl = base + s;
    if (i < n) g_off[i] = incl - v;            // exclusive within block
    if (threadIdx.x == SCAN_B - 1) g_part[blockIdx.x] = incl;
}

// pass 2 (fused): each block reduces g_part[0..blockIdx) inline, then finalizes
// offsets, cursors and dinv. Requires gridDim.x <= SCAN_B (196 <= 512 here).
__global__ __launch_bounds__(SCAN_B) void k_scan3(int n, int e) {
    __shared__ int warp_red[SCAN_B / 32];
    __shared__ int s_base;
    int b = blockIdx.x;
    int tid = threadIdx.x, lane = tid & 31, wid = tid >> 5;

    int v = (tid < b) ? g_part[tid] : 0;
    #pragma unroll
    for (int d = 16; d > 0; d >>= 1) v += __shfl_down_sync(0xffffffffu, v, d);
    if (lane == 0) warp_red[wid] = v;
    __syncthreads();
    if (wid == 0) {
        int t = (lane < SCAN_B / 32) ? warp_red[lane] : 0;
        #pragma unroll
        for (int d = 8; d > 0; d >>= 1) t += __shfl_down_sync(0xffffffffu, t, d);
        if (lane == 0) s_base = t;
    }
    __syncthreads();
    int base = s_base;

    int i = b * SCAN_B + tid;
    if (i < n) {
        int o = g_off[i] + base;
        g_off[i] = o;
        g_cur[i] = o;
        g_dinv[i] = rsqrtf((float)(g_deg[i] + 1));
    }
    if (i == 0) g_off[n] = e;
}

__global__ void k_fill(const int* __restrict__ src, const int* __restrict__ dst, int e) {
    int i = blockIdx.x * blockDim.x + threadIdx.x;
    if (i < e) {
        int d = dst[i];
        if (d >= 0 && d < NMAX) {
            int pos = atomicAdd(&g_cur[d], 1);
            if (pos >= 0 && pos < EMAX) g_csr[pos] = src[i];
        }
    }
}

// ---------- GEMMs (packed f32x2 FMA, branch B) ----------
#define SXS 68   // padded row stride for sX (kills 2-way bank conflict)

// out = x @ W_pre + b      x:[n,128]  W:[128,64]  (fp32 out = ori_x)
__global__ __launch_bounds__(256) void k_gemm_pre(
    const float* __restrict__ x, const float* __restrict__ W,
    const float* __restrict__ b, float* __restrict__ out, int n)
{
    __shared__ float sX[64 * SXS];
    __shared__ float sW[64 * 64];
    int row0 = blockIdx.x * 64;
    int t = threadIdx.x;
    int tx = t & 15, ty = t >> 4;

    unsigned long long acc[4][2] = {};

    for (int kc = 0; kc < 2; kc++) {
        if (kc) __syncthreads();
        #pragma unroll
        for (int it = 0; it < 4; it++) {
            int idx = t + it * 256;
            int r = idx >> 4, c4 = idx & 15;
            float4 v = make_float4(0.f, 0.f, 0.f, 0.f);
            if (row0 + r < n)
                v = *reinterpret_cast<const float4*>(&x[(size_t)(row0 + r) * 128 + kc * 64 + c4 * 4]);
            *reinterpret_cast<float4*>(&sX[r * SXS + c4 * 4]) = v;
            *reinterpret_cast<float4*>(&sW[r * 64 + c4 * 4]) =
                *reinterpret_cast<const float4*>(&W[(size_t)(kc * 64 + r) * 64 + c4 * 4]);
        }
        __syncthreads();
        #pragma unroll 8
        for (int k = 0; k < 64; k++) {
            ulonglong2 w = *reinterpret_cast<ulonglong2*>(&sW[k * 64 + tx * 4]);
            #pragma unroll
            for (int i = 0; i < 4; i++) {
                unsigned long long ap = pack2(sX[(ty * 4 + i) * SXS + k]);
                fma2(acc[i][0], ap, w.x);
                fma2(acc[i][1], ap, w.y);
            }
        }
    }

    float4 bb = *reinterpret_cast<const float4*>(&b[tx * 4]);
    #pragma unroll
    for (int i = 0; i < 4; i++) {
        int r = row0 + ty * 4 + i;
        if (r < n) {
            float2 lo = unpack2(acc[i][0]);
            float2 hi = unpack2(acc[i][1]);
            float4 o = make_float4(lo.x + bb.x, lo.y + bb.y, hi.x + bb.z, hi.y + bb.w);
            *reinterpret_cast<float4*>(&out[(size_t)r * HD + tx * 4]) = o;
        }
    }
}

// g_sh = fp16( in @ W )    in:[n,64] fp32  W:[64,64]   (no dinv — applied in gather)
__global__ __launch_bounds__(256) void k_gemm64(
    const float* __restrict__ in, const float* __restrict__ W, int n)
{
    __shared__ float sX[64 * SXS];
    __shared__ float sW[64 * 64];
    int row0 = blockIdx.x * 64;
    int t = threadIdx.x;
    int tx = t & 15, ty = t >> 4;

    #pragma unroll
    for (int it = 0; it < 4; it++) {
        int idx = t + it * 256;
        int r = idx >> 4, c4 = idx & 15;
        float4 v = make_float4(0.f, 0.f, 0.f, 0.f);
        if (row0 + r < n)
            v = *reinterpret_cast<const float4*>(&in[(size_t)(row0 + r) * 64 + c4 * 4]);
        *reinterpret_cast<float4*>(&sX[r * SXS + c4 * 4]) = v;
        *reinterpret_cast<float4*>(&sW[r * 64 + c4 * 4]) =
            *reinterpret_cast<const float4*>(&W[(size_t)r * 64 + c4 * 4]);
    }
    __syncthreads();

    unsigned long long acc[4][2] = {};
    #pragma unroll 8
    for (int k = 0; k < 64; k++) {
        ulonglong2 w = *reinterpret_cast<ulonglong2*>(&sW[k * 64 + tx * 4]);
        #pragma unroll
        for (int i = 0; i < 4; i++) {
            unsigned long long ap = pack2(sX[(ty * 4 + i) * SXS + k]);
            fma2(acc[i][0], ap, w.x);
            fma2(acc[i][1], ap, w.y);
        }
    }

    #pragma unroll
    for (int i = 0; i < 4; i++) {
        int r = row0 + ty * 4 + i;
        if (r < n) {
            float2 lo = unpack2(acc[i][0]);
            float2 hi = unpack2(acc[i][1]);
            __half2 h0 = __floats2half2_rn(lo.x, lo.y);
            __half2 h1 = __floats2half2_rn(hi.x, hi.y);
            uint2 o;
            o.x = *reinterpret_cast<unsigned int*>(&h0);
            o.y = *reinterpret_cast<unsigned int*>(&h1);
            *reinterpret_cast<uint2*>(&g_sh[(size_t)r * HD + tx * 4]) = o;
        }
    }
}

// load 4 halfs of s[u] at column c, as float4
__device__ __forceinline__ float4 ld_s4(int u, int c) {
    uint2 p = *reinterpret_cast<const uint2*>(&g_sh[(size_t)u * HD + c]);
    __half2 a = *reinterpret_cast<__half2*>(&p.x);
    __half2 b = *reinterpret_cast<__half2*>(&p.y);
    float2 fa = __half22float2(a), fb = __half22float2(b);
    return make_float4(fa.x, fa.y, fb.x, fb.y);
}

// ---------- fused pull-gather + norm + bias + relu ----------
// out[v] = relu(dinv[v] * (sum_{u in N(v)} dinv[u]*s[u] + dinv[v]*s[v]) + b)
__global__ __launch_bounds__(256) void k_gather(
    const float* __restrict__ b, float* __restrict__ out, int n)
{
    int v = blockIdx.x * 16 + (threadIdx.x >> 4);
    if (v >= n) return;
    int c = (threadIdx.x & 15) * 4;

    int beg = g_off[v];
    int end = g_off[v + 1];

    float dv = g_dinv[v];
    float4 sv = ld_s4(v, c);    // self-loop
    float4 acc = make_float4(dv * sv.x, dv * sv.y, dv * sv.z, dv * sv.w);

    int j = beg;
    for (; j + 4 <= end; j += 4) {
        int u0 = __ldg(&g_csr[j]);
        int u1 = __ldg(&g_csr[j + 1]);
        int u2 = __ldg(&g_csr[j + 2]);
        int u3 = __ldg(&g_csr[j + 3]);
        float d0 = __ldg(&g_dinv[u0]);
        float d1 = __ldg(&g_dinv[u1]);
        float d2 = __ldg(&g_dinv[u2]);
        float d3 = __ldg(&g_dinv[u3]);
        float4 a0 = ld_s4(u0, c);
        float4 a1 = ld_s4(u1, c);
        float4 a2 = ld_s4(u2, c);
        float4 a3 = ld_s4(u3, c);
        acc.x += (d0 * a0.x + d1 * a1.x) + (d2 * a2.x + d3 * a3.x);
        acc.y += (d0 * a0.y + d1 * a1.y) + (d2 * a2.y + d3 * a3.y);
        acc.z += (d0 * a0.z + d1 * a1.z) + (d2 * a2.z + d3 * a3.z);
        acc.w += (d0 * a0.w + d1 * a1.w) + (d2 * a2.w + d3 * a3.w);
    }
    for (; j < end; j++) {
        int u = __ldg(&g_csr[j]);
        float d = __ldg(&g_dinv[u]);
        float4 a = ld_s4(u, c);
        acc.x += d * a.x; acc.y += d * a.y; acc.z += d * a.z; acc.w += d * a.w;
    }

    float4 bb = *reinterpret_cast<const float4*>(&b[c]);
    float4 o;
    o.x = fmaxf(fmaf(dv, acc.x, bb.x), 0.f);
    o.y = fmaxf(fmaf(dv, acc.y, bb.y), 0.f);
    o.z = fmaxf(fmaf(dv, acc.z, bb.z), 0.f);
    o.w = fmaxf(fmaf(dv, acc.w, bb.w), 0.f);
    *reinterpret_cast<float4*>(&out[(size_t)v * HD + c]) = o;
}

extern "C" void kernel_launch(void* const* d_in, const int* in_sizes, int n_in,
                              void* d_out, int out_size) {
    const float* x     = (const float*)d_in[0];
    const int*   eidx  = (const int*)  d_in[1];
    const float* W_pre = (const float*)d_in[2];
    const float* b_pre = (const float*)d_in[3];
    const float* W1    = (const float*)d_in[4];
    const float* b1    = (const float*)d_in[5];
    const float* W2    = (const float*)d_in[6];
    const float* b2    = (const float*)d_in[7];
    float* out = (float*)d_out;

    int n = in_sizes[0] / 128;
    int e = in_sizes[1] / 2;
    const int* src = eidx;
    const int* dst = eidx + e;

    float* x_out = out;                    // layer-2 output
    float* ori_x = out + (size_t)n * HD;   // pre-linear output

    float* h_buf = nullptr;
    cudaGetSymbolAddress((void**)&h_buf, g_h);

    const int T = 256;
    int gb_n = (n + T - 1) / T;
    int gb_e = (e + T - 1) / T;
    int gb_g = (n + 63) / 64;
    int nb   = (n + SCAN_B - 1) / SCAN_B;
    int gb_a = (n + 15) / 16;

    // Fork: CSR build on side stream, GEMM chain on main (capture) stream.
    // Host objects are created per call and intentionally not destroyed
    // (kernel_launch runs O(1) times; destroying during capture is hazardous).
    cudaStream_t s2;
    cudaStreamCreateWithFlags(&s2, cudaStreamNonBlocking);
    cudaEvent_t evFork, evA;
    cudaEventCreateWithFlags(&evFork, cudaEventDisableTiming);
    cudaEventCreateWithFlags(&evA, cudaEventDisableTiming);

    cudaEventRecord(evFork, 0);
    cudaStreamWaitEvent(s2, evFork, 0);

    // branch A (s2): CSR build + dinv
    k_zero_deg<<<gb_n, T, 0, s2>>>(n);
    k_count<<<gb_e, T, 0, s2>>>(dst, e);
    k_scan1<<<nb, SCAN_B, 0, s2>>>(n);
    k_scan3<<<nb, SCAN_B, 0, s2>>>(n, e);
    k_fill<<<gb_e, T, 0, s2>>>(src, dst, e);
    cudaEventRecord(evA, s2);

    // branch B (main): pre-linear + layer-1 GEMM (no CSR dependence)
    k_gemm_pre<<<gb_g, T>>>(x, W_pre, b_pre, ori_x, n);
    k_gemm64<<<gb_g, T>>>(ori_x, W1, n);

    // join, then the graph-dependent part
    cudaStreamWaitEvent(0, evA, 0);
    k_gather<<<gb_a, T>>>(b1, h_buf, n);

    k_gemm64<<<gb_g, T>>>(h_buf, W2, n);
    k_gather<<<gb_a, T>>>(b2, x_out, n);
}

// round 11
// speedup vs baseline: 1.6163x; 1.0032x over previous
#include <cuda_runtime.h>
#include <cuda_fp16.h>

#define HD 64
static const int NMAX = 100000;
static const int EMAX = 1200000;

// Scratch (allocation-free per harness rules)
__device__ int    g_deg[NMAX];
__device__ int    g_off[NMAX + 1];
__device__ int    g_cur[NMAX];
__device__ int    g_part[1024];
__device__ int    g_csr[EMAX];
__device__ float  g_dinv[NMAX];
__device__ __half g_sh[NMAX * HD];    // fp16: layer-1 messages (ori_x @ W1)
__device__ __half g_sh2[NMAX * HD];   // fp16: layer-2 messages (h @ W2)

// ---------- packed f32x2 helpers ----------
__device__ __forceinline__ unsigned long long pack2(float a) {
    unsigned long long r;
    asm("mov.b64 %0, {%1, %1};" : "=l"(r) : "f"(a));
    return r;
}
__device__ __forceinline__ void fma2(unsigned long long& d,
                                     unsigned long long a,
                                     unsigned long long b) {
    asm("fma.rn.f32x2 %0, %1, %2, %0;" : "+l"(d) : "l"(a), "l"(b));
}
__device__ __forceinline__ float2 unpack2(unsigned long long v) {
    float2 u;
    asm("mov.b64 {%0, %1}, %2;" : "=f"(u.x), "=f"(u.y) : "l"(v));
    return u;
}

// ---------- graph preprocessing (branch A, overlapped) ----------
__global__ void k_zero_deg(int n) {
    int i = blockIdx.x * blockDim.x + threadIdx.x;
    if (i < n) g_deg[i] = 0;
}

__global__ void k_count(const int* __restrict__ dst, int e) {
    int i = blockIdx.x * blockDim.x + threadIdx.x;
    if (i < e) {
        int d = dst[i];
        if (d >= 0 && d < NMAX) atomicAdd(&g_deg[d], 1);
    }
}

#define SCAN_B 512
__global__ __launch_bounds__(SCAN_B) void k_scan1(int n) {
    __shared__ int warp_sums[SCAN_B / 32];
    int i = blockIdx.x * SCAN_B + threadIdx.x;
    int v = (i < n) ? g_deg[i] : 0;
    int lane = threadIdx.x & 31, wid = threadIdx.x >> 5;

    int s = v;
    #pragma unroll
    for (int d = 1; d < 32; d <<= 1) {
        int t = __shfl_up_sync(0xffffffffu, s, d);
        if (lane >= d) s += t;
    }
    if (lane == 31) warp_sums[wid] = s;
    __syncthreads();
    if (wid == 0) {
        int ws = (lane < SCAN_B / 32) ? warp_sums[lane] : 0;
        #pragma unroll
        for (int d = 1; d < SCAN_B / 32; d <<= 1) {
            int t = __shfl_up_sync(0xffffffffu, ws, d);
            if (lane >= d) ws += t;
        }
        if (lane < SCAN_B / 32) warp_sums[lane] = ws;
    }
    __syncthreads();
    int base = (wid > 0) ? warp_sums[wid - 1] : 0;
    int incl = base + s;
    if (i < n) g_off[i] = incl - v;
    if (threadIdx.x == SCAN_B - 1) g_part[blockIdx.x] = incl;
}

// fused pass 2+3: reduce g_part[0..blockIdx) inline, finalize offsets/cursors/dinv
__global__ __launch_bounds__(SCAN_B) void k_scan3(int n, int e) {
    __shared__ int warp_red[SCAN_B / 32];
    __shared__ int s_base;
    int b = blockIdx.x;
    int tid = threadIdx.x, lane = tid & 31, wid = tid >> 5;

    int v = (tid < b) ? g_part[tid] : 0;
    #pragma unroll
    for (int d = 16; d > 0; d >>= 1) v += __shfl_down_sync(0xffffffffu, v, d);
    if (lane == 0) warp_red[wid] = v;
    __syncthreads();
    if (wid == 0) {
        int t = (lane < SCAN_B / 32) ? warp_red[lane] : 0;
        #pragma unroll
        for (int d = 8; d > 0; d >>= 1) t += __shfl_down_sync(0xffffffffu, t, d);
        if (lane == 0) s_base = t;
    }
    __syncthreads();
    int base = s_base;

    int i = b * SCAN_B + tid;
    if (i < n) {
        int o = g_off[i] + base;
        g_off[i] = o;
        g_cur[i] = o;
        g_dinv[i] = rsqrtf((float)(g_deg[i] + 1));
    }
    if (i == 0) g_off[n] = e;
}

__global__ void k_fill(const int* __restrict__ src, const int* __restrict__ dst, int e) {
    int i = blockIdx.x * blockDim.x + threadIdx.x;
    if (i < e) {
        int d = dst[i];
        if (d >= 0 && d < NMAX) {
            int pos = atomicAdd(&g_cur[d], 1);
            if (pos >= 0 && pos < EMAX) g_csr[pos] = src[i];
        }
    }
}

// ---------- shared helpers ----------
#define SXS 68   // padded row stride for sX

__device__ __forceinline__ float4 ld_half4(const __half* base, int u, int c) {
    uint2 p = *reinterpret_cast<const uint2*>(&base[(size_t)u * HD + c]);
    __half2 a = *reinterpret_cast<__half2*>(&p.x);
    __half2 b = *reinterpret_cast<__half2*>(&p.y);
    float2 fa = __half22float2(a), fb = __half22float2(b);
    return make_float4(fa.x, fa.y, fb.x, fb.y);
}

// sX[64 x 64 fp32, stride SXS] @ sW[64 x 64] -> acc (thread (tx,ty): rows ty*4+i, col-quad tx)
__device__ __forceinline__ void gemm_tile(const float* sX, const float* sW,
                                          unsigned long long acc[4][2],
                                          int tx, int ty) {
    #pragma unroll 8
    for (int k = 0; k < 64; k++) {
        ulonglong2 w = *reinterpret_cast<const ulonglong2*>(&sW[k * 64 + tx * 4]);
        #pragma unroll
        for (int i = 0; i < 4; i++) {
            unsigned long long ap = pack2(sX[(ty * 4 + i) * SXS + k]);
            fma2(acc[i][0], ap, w.x);
            fma2(acc[i][1], ap, w.y);
        }
    }
}

__device__ __forceinline__ void store_half4(__half* base, int r, int tx,
                                            unsigned long long a0,
                                            unsigned long long a1) {
    float2 lo = unpack2(a0);
    float2 hi = unpack2(a1);
    __half2 h0 = __floats2half2_rn(lo.x, lo.y);
    __half2 h1 = __floats2half2_rn(hi.x, hi.y);
    uint2 o;
    o.x = *reinterpret_cast<unsigned int*>(&h0);
    o.y = *reinterpret_cast<unsigned int*>(&h1);
    *reinterpret_cast<uint2*>(&base[(size_t)r * HD + tx * 4]) = o;
}

// ---------- fused: (x @ W_pre + b_pre) -> ori_x ; tile @ W1 -> g_sh ----------
__global__ __launch_bounds__(256) void k_fused_pre_w1(
    const float* __restrict__ x, const float* __restrict__ Wp,
    const float* __restrict__ bp, const float* __restrict__ W1,
    float* __restrict__ ori_x, int n)
{
    __shared__ float sX[64 * SXS];
    __shared__ float sW[64 * 64];
    int row0 = blockIdx.x * 64;
    int t = threadIdx.x;
    int tx = t & 15, ty = t >> 4;

    unsigned long long acc[4][2] = {};

    for (int kc = 0; kc < 2; kc++) {
        if (kc) __syncthreads();
        #pragma unroll
        for (int it = 0; it < 4; it++) {
            int idx = t + it * 256;
            int r = idx >> 4, c4 = idx & 15;
            float4 v = make_float4(0.f, 0.f, 0.f, 0.f);
            if (row0 + r < n)
                v = *reinterpret_cast<const float4*>(&x[(size_t)(row0 + r) * 128 + kc * 64 + c4 * 4]);
            *reinterpret_cast<float4*>(&sX[r * SXS + c4 * 4]) = v;
            *reinterpret_cast<float4*>(&sW[r * 64 + c4 * 4]) =
                *reinterpret_cast<const float4*>(&Wp[(size_t)(kc * 64 + r) * 64 + c4 * 4]);
        }
        __syncthreads();
        gemm_tile(sX, sW, acc, tx, ty);
    }

    // epilogue 1: +bias, write ori_x, park tile in sX, load W1
    __syncthreads();
    float4 bb = *reinterpret_cast<const float4*>(&bp[tx * 4]);
    #pragma unroll
    for (int i = 0; i < 4; i++) {
        float2 lo = unpack2(acc[i][0]);
        float2 hi = unpack2(acc[i][1]);
        float4 o = make_float4(lo.x + bb.x, lo.y + bb.y, hi.x + bb.z, hi.y + bb.w);
        int r = row0 + ty * 4 + i;
        *reinterpret_cast<float4*>(&sX[(ty * 4 + i) * SXS + tx * 4]) = o;
        if (r < n)
            *reinterpret_cast<float4*>(&ori_x[(size_t)r * HD + tx * 4]) = o;
    }
    #pragma unroll
    for (int it = 0; it < 4; it++) {
        int idx = t + it * 256;
        int r = idx >> 4, c4 = idx & 15;
        *reinterpret_cast<float4*>(&sW[r * 64 + c4 * 4]) =
            *reinterpret_cast<const float4*>(&W1[(size_t)r * 64 + c4 * 4]);
    }
    __syncthreads();

    // phase 2: g_sh = tile @ W1 (fp16)
    unsigned long long acc2[4][2] = {};
    gemm_tile(sX, sW, acc2, tx, ty);
    #pragma unroll
    for (int i = 0; i < 4; i++) {
        int r = row0 + ty * 4 + i;
        if (r < n) store_half4(g_sh, r, tx, acc2[i][0], acc2[i][1]);
    }
}

// ---------- fused: gather layer-1 -> h (smem) ; h @ W2 -> g_sh2 ----------
__global__ __launch_bounds__(256) void k_fused_gather_w2(
    const float* __restrict__ b1, const float* __restrict__ W2, int n)
{
    __shared__ float sX[64 * SXS];
    __shared__ float sW[64 * 64];
    int row0 = blockIdx.x * 64;
    int t = threadIdx.x;
    int tx = t & 15, ty = t >> 4;
    int grp = t >> 4;
    int c = (t & 15) * 4;

    float4 bb1 = *reinterpret_cast<const float4*>(&b1[c]);
    #pragma unroll
    for (int it = 0; it < 4; it++) {
        int lr = grp + it * 16;
        int v = row0 + lr;
        float4 h = make_float4(0.f, 0.f, 0.f, 0.f);
        if (v < n) {
            int beg = g_off[v];
            int end = g_off[v + 1];
            float dv = g_dinv[v];
            float4 sv = ld_half4(g_sh, v, c);
            float4 acc = make_float4(dv * sv.x, dv * sv.y, dv * sv.z, dv * sv.w);

            int j = beg;
            for (; j + 4 <= end; j += 4) {
                int u0 = __ldg(&g_csr[j]);
                int u1 = __ldg(&g_csr[j + 1]);
                int u2 = __ldg(&g_csr[j + 2]);
                int u3 = __ldg(&g_csr[j + 3]);
                float d0 = __ldg(&g_dinv[u0]);
                float d1 = __ldg(&g_dinv[u1]);
                float d2 = __ldg(&g_dinv[u2]);
                float d3 = __ldg(&g_dinv[u3]);
                float4 a0 = ld_half4(g_sh, u0, c);
                float4 a1 = ld_half4(g_sh, u1, c);
                float4 a2 = ld_half4(g_sh, u2, c);
                float4 a3 = ld_half4(g_sh, u3, c);
                acc.x += (d0 * a0.x + d1 * a1.x) + (d2 * a2.x + d3 * a3.x);
                acc.y += (d0 * a0.y + d1 * a1.y) + (d2 * a2.y + d3 * a3.y);
                acc.z += (d0 * a0.z + d1 * a1.z) + (d2 * a2.z + d3 * a3.z);
                acc.w += (d0 * a0.w + d1 * a1.w) + (d2 * a2.w + d3 * a3.w);
            }
            for (; j < end; j++) {
                int u = __ldg(&g_csr[j]);
                float d = __ldg(&g_dinv[u]);
                float4 a = ld_half4(g_sh, u, c);
                acc.x += d * a.x; acc.y += d * a.y; acc.z += d * a.z; acc.w += d * a.w;
            }
            h.x = fmaxf(fmaf(dv, acc.x, bb1.x), 0.f);
            h.y = fmaxf(fmaf(dv, acc.y, bb1.y), 0.f);
            h.z = fmaxf(fmaf(dv, acc.z, bb1.z), 0.f);
            h.w = fmaxf(fmaf(dv, acc.w, bb1.w), 0.f);
        }
        *reinterpret_cast<float4*>(&sX[lr * SXS + c]) = h;
    }

    #pragma unroll
    for (int it = 0; it < 4; it++) {
        int idx = t + it * 256;
        int r = idx >> 4, c4 = idx & 15;
        *reinterpret_cast<float4*>(&sW[r * 64 + c4 * 4]) =
            *reinterpret_cast<const float4*>(&W2[(size_t)r * 64 + c4 * 4]);
    }
    __syncthreads();

    unsigned long long acc2[4][2] = {};
    gemm_tile(sX, sW, acc2, tx, ty);
    #pragma unroll
    for (int i = 0; i < 4; i++) {
        int r = row0 + ty * 4 + i;
        if (r < n) store_half4(g_sh2, r, tx, acc2[i][0], acc2[i][1]);
    }
}

// ---------- final gather on g_sh2 -> x_out ----------
__global__ __launch_bounds__(256) void k_gather_final(
    const float* __restrict__ b, float* __restrict__ out, int n)
{
    int v = blockIdx.x * 16 + (threadIdx.x >> 4);
    if (v >= n) return;
    int c = (threadIdx.x & 15) * 4;

    int beg = g_off[v];
    int end = g_off[v + 1];

    float dv = g_dinv[v];
    float4 sv = ld_half4(g_sh2, v, c);
    float4 acc = make_float4(dv * sv.x, dv * sv.y, dv * sv.z, dv * sv.w);

    int j = beg;
    for (; j + 4 <= end; j += 4) {
        int u0 = __ldg(&g_csr[j]);
        int u1 = __ldg(&g_csr[j + 1]);
        int u2 = __ldg(&g_csr[j + 2]);
        int u3 = __ldg(&g_csr[j + 3]);
        float d0 = __ldg(&g_dinv[u0]);
        float d1 = __ldg(&g_dinv[u1]);
        float d2 = __ldg(&g_dinv[u2]);
        float d3 = __ldg(&g_dinv[u3]);
        float4 a0 = ld_half4(g_sh2, u0, c);
        float4 a1 = ld_half4(g_sh2, u1, c);
        float4 a2 = ld_half4(g_sh2, u2, c);
        float4 a3 = ld_half4(g_sh2, u3, c);
        acc.x += (d0 * a0.x + d1 * a1.x) + (d2 * a2.x + d3 * a3.x);
        acc.y += (d0 * a0.y + d1 * a1.y) + (d2 * a2.y + d3 * a3.y);
        acc.z += (d0 * a0.z + d1 * a1.z) + (d2 * a2.z + d3 * a3.z);
        acc.w += (d0 * a0.w + d1 * a1.w) + (d2 * a2.w + d3 * a3.w);
    }
    for (; j < end; j++) {
        int u = __ldg(&g_csr[j]);
        float d = __ldg(&g_dinv[u]);
        float4 a = ld_half4(g_sh2, u, c);
        acc.x += d * a.x; acc.y += d * a.y; acc.z += d * a.z; acc.w += d * a.w;
    }

    float4 bb = *reinterpret_cast<const float4*>(&b[c]);
    float4 o;
    o.x = fmaxf(fmaf(dv, acc.x, bb.x), 0.f);
    o.y = fmaxf(fmaf(dv, acc.y, bb.y), 0.f);
    o.z = fmaxf(fmaf(dv, acc.z, bb.z), 0.f);
    o.w = fmaxf(fmaf(dv, acc.w, bb.w), 0.f);
    *reinterpret_cast<float4*>(&out[(size_t)v * HD + c]) = o;
}

extern "C" void kernel_launch(void* const* d_in, const int* in_sizes, int n_in,
                              void* d_out, int out_size) {
    const float* x     = (const float*)d_in[0];
    const int*   eidx  = (const int*)  d_in[1];
    const float* W_pre = (const float*)d_in[2];
    const float* b_pre = (const float*)d_in[3];
    const float* W1    = (const float*)d_in[4];
    const float* b1    = (const float*)d_in[5];
    const float* W2    = (const float*)d_in[6];
    const float* b2    = (const float*)d_in[7];
    float* out = (float*)d_out;

    int n = in_sizes[0] / 128;
    int e = in_sizes[1] / 2;
    const int* src = eidx;
    const int* dst = eidx + e;

    float* x_out = out;
    float* ori_x = out + (size_t)n * HD;

    const int T = 256;
    int gb_n = (n + T - 1) / T;
    int gb_e = (e + T - 1) / T;
    int gb_g = (n + 63) / 64;
    int nb   = (n + SCAN_B - 1) / SCAN_B;
    int gb_a = (n + 15) / 16;

    // Fork: CSR build on side stream; fused GEMM on main (capture) stream.
    // Host stream/event objects created per call, intentionally not destroyed.
    cudaStream_t s2;
    cudaStreamCreateWithFlags(&s2, cudaStreamNonBlocking);
    cudaEvent_t evFork, evA;
    cudaEventCreateWithFlags(&evFork, cudaEventDisableTiming);
    cudaEventCreateWithFlags(&evA, cudaEventDisableTiming);

    cudaEventRecord(evFork, 0);
    cudaStreamWaitEvent(s2, evFork, 0);

    // branch A (s2): CSR build + dinv
    k_zero_deg<<<gb_n, T, 0, s2>>>(n);
    k_count<<<gb_e, T, 0, s2>>>(dst, e);
    k_scan1<<<nb, SCAN_B, 0, s2>>>(n);
    k_scan3<<<nb, SCAN_B, 0, s2>>>(n, e);
    k_fill<<<gb_e, T, 0, s2>>>(src, dst, e);
    cudaEventRecord(evA, s2);

    // branch B (main): fused pre-linear + layer-1 GEMM
    k_fused_pre_w1<<<gb_g, T>>>(x, W_pre, b_pre, W1, ori_x, n);

    // join, then graph-dependent fused layer + final gather
    cudaStreamWaitEvent(0, evA, 0);
    k_fused_gather_w2<<<gb_g, T>>>(b1, W2, n);
    k_gather_final<<<gb_a, T>>>(b2, x_out, n);
}